// round 15
// baseline (speedup 1.0000x reference)
#include <cuda_runtime.h>

// ---------------------------------------------------------------------------
// MOE_DISTRIBUTE_CASCADE_GRAPH — two PLAIN launches (R13 structure):
//   K1: wide rank — one block per 256-id chunk; chunk-local stable ranks via
//       one __match_any_sync step + per-chunk hist; ticket-elected LAST block
//       runs a TWO-PASS scan that folds the expert base INTO g_base, so
//       combine needs only:  inv[i] = local_rank[i] + g_base[e][i>>8].
//   K2: combine — R13-measured-best geometry (256 thr, 2 float4 cols/thread,
//       8192 blocks, 85.6% DRAM), one fewer dependent load in the head.
// ---------------------------------------------------------------------------

#define NBINS   256        // max experts supported (dataset uses 64)
#define NCHUNK  256        // max chunks (chunk = 256 ids -> N <= 65536)
#define CHSZ    256        // ids per chunk == threads per K1 block
#define MAXN    (NCHUNK * CHSZ)

__device__ int g_inv[MAXN];              // chunk-local ranks
__device__ int g_hist[NBINS * NCHUNK];   // [expert][chunk]  (expert-major)
__device__ int g_base[NBINS * NCHUNK];   // expert_base + exclusive chunk prefix
__device__ unsigned g_ctr = 0;           // last-block ticket (self-resetting)

// --- K1: chunk-local stable ranks + hist; last block: fused 2-pass scan -----
__global__ void __launch_bounds__(CHSZ, 4)
rank_wide_kernel(const int* __restrict__ ids, int n, int nchunk) {
    __shared__ int cnt[8 * NBINS];
    __shared__ int totals[NBINS];
    __shared__ int is_last;
    const unsigned FULL = 0xffffffffu;
    const int blk  = blockIdx.x;
    const int tid  = threadIdx.x;
    const int w    = tid >> 5;
    const int lane = tid & 31;
    const int i    = blk * CHSZ + tid;

    for (int j = tid; j < 8 * NBINS; j += CHSZ) cnt[j] = 0;
    __syncthreads();

    // one match step per warp -> warp-local count/rank
    const bool valid = (i < n);
    const int  key   = valid ? ids[i] : (NBINS + lane);
    const unsigned mask = __match_any_sync(FULL, key);
    const int lower  = __popc(mask & ((1u << lane) - 1u));
    const int leader = __ffs(mask) - 1;
    if (valid && lane == leader)
        cnt[w * NBINS + key] = __popc(mask);
    __syncthreads();

    // per-expert exclusive scan over the 8 warp rows; totals -> g_hist
    {
        int run = 0;
        #pragma unroll
        for (int ww = 0; ww < 8; ww++) {
            const int h = cnt[ww * NBINS + tid];
            cnt[ww * NBINS + tid] = run;
            run += h;
        }
        g_hist[tid * NCHUNK + blk] = run;        // expert-major
    }
    __syncthreads();

    if (valid) g_inv[i] = lower + cnt[w * NBINS + key];

    // publish, then elect the last block
    __threadfence();
    __syncthreads();
    if (tid == 0)
        is_last = (atomicAdd(&g_ctr, 1u) == (unsigned)gridDim.x - 1u);
    __syncthreads();

    if (is_last) {
        __threadfence();                          // acquire all blocks' writes

        const int4* hrow = reinterpret_cast<const int4*>(&g_hist[tid * NCHUNK]);
        int4*       brow = reinterpret_cast<int4*>(&g_base[tid * NCHUNK]);
        const bool  vec  = ((nchunk & 3) == 0);

        // pass 1: row totals (vectorized reduce, no prefix writes yet)
        int tot = 0;
        if (vec) {
            #pragma unroll 8
            for (int c4 = 0; c4 < (nchunk >> 2); c4++) {
                const int4 h = hrow[c4];
                tot += h.x + h.y + h.z + h.w;
            }
        } else {
            for (int c = 0; c < nchunk; c++)
                tot += g_hist[tid * NCHUNK + c];
        }
        totals[tid] = tot;
        __syncthreads();

        // inclusive Hillis-Steele over expert totals (256 threads)
        #pragma unroll
        for (int d = 1; d < NBINS; d <<= 1) {
            const int v = (tid >= d) ? totals[tid - d] : 0;
            __syncthreads();
            totals[tid] += v;
            __syncthreads();
        }
        // pass 2: write g_base = expert_base + chunk prefix (bases folded in)
        int run = (tid == 0) ? 0 : totals[tid - 1];
        if (vec) {
            #pragma unroll 8
            for (int c4 = 0; c4 < (nchunk >> 2); c4++) {
                const int4 h = hrow[c4];
                int4 bo;
                bo.x = run;
                bo.y = bo.x + h.x;
                bo.z = bo.y + h.y;
                bo.w = bo.z + h.z;
                run  = bo.w + h.w;
                brow[c4] = bo;
            }
        } else {
            for (int c = 0; c < nchunk; c++) {
                const int h = g_hist[tid * NCHUNK + c];
                g_base[tid * NCHUNK + c] = run;
                run += h;
            }
        }
        if (tid == 0) g_ctr = 0;                  // re-arm for next replay
    }
}

// --- K2: combine (R13-measured-best geometry) + single-load reconstruction --
template <int K, bool GUARD>
__global__ void __launch_bounds__(256, 4)
combine_kernel(const int* __restrict__ ids,
               const float* __restrict__ G,
               const float* __restrict__ scales,
               float* __restrict__ out,
               int B, int H4, int dup) {
    const int b  = blockIdx.y;
    const int h0 = blockIdx.x * 512 + threadIdx.x;
    const int h1 = h0 + 256;
    __shared__ int   rows[K];
    __shared__ float sc[K];
    if (threadIdx.x < K) {
        const int i = b * K + threadIdx.x;
        // independent loads first ...
        const int e  = __ldg(&ids[i]);
        const int lr = __ldg(&g_inv[i]);
        sc[threadIdx.x] = __ldg(&scales[i]);
        // ... one e-dependent load (expert base already folded into g_base)
        rows[threadIdx.x] = lr + __ldg(&g_base[e * NCHUNK + (i >> 8)]);
    }
    __syncthreads();

    const float4* __restrict__ Gv = reinterpret_cast<const float4*>(G);
    float4* __restrict__ ov = reinterpret_cast<float4*>(out);

    const bool v0 = GUARD ? (h0 < H4) : true;
    const bool v1 = GUARD ? (h1 < H4) : true;
    float4 acc0 = make_float4(0.f, 0.f, 0.f, 0.f);
    float4 acc1 = make_float4(0.f, 0.f, 0.f, 0.f);
    #pragma unroll
    for (int k = 0; k < K; k++) {
        const float  s  = sc[k];
        const size_t rb = (size_t)rows[k] * H4;
        if (v0) {
            const float4 a = __ldg(&Gv[rb + h0]);
            acc0.x = fmaf(s, a.x, acc0.x);
            acc0.y = fmaf(s, a.y, acc0.y);
            acc0.z = fmaf(s, a.z, acc0.z);
            acc0.w = fmaf(s, a.w, acc0.w);
        }
        if (v1) {
            const float4 c = __ldg(&Gv[rb + h1]);
            acc1.x = fmaf(s, c.x, acc1.x);
            acc1.y = fmaf(s, c.y, acc1.y);
            acc1.z = fmaf(s, c.z, acc1.z);
            acc1.w = fmaf(s, c.w, acc1.w);
        }
    }
    const size_t ob = (size_t)b * H4;
    if (v0) ov[ob + h0] = acc0;
    if (v1) ov[ob + h1] = acc1;
    if (dup) {
        const size_t od = (size_t)B * H4 + ob;
        if (v0) ov[od + h0] = acc0;
        if (v1) ov[od + h1] = acc1;
    }
}

// generic-K fallback (same single-load reconstruction)
__global__ void __launch_bounds__(256, 4)
combine_kernel_gen(const int* __restrict__ ids,
                   const float* __restrict__ G,
                   const float* __restrict__ scales,
                   float* __restrict__ out,
                   int B, int K, int H4, int dup) {
    const int b = blockIdx.y;
    const int h = blockIdx.x * 256 + threadIdx.x;
    __shared__ int   rows[32];
    __shared__ float sc[32];
    if (threadIdx.x < (unsigned)K) {
        const int i = b * K + threadIdx.x;
        const int e = ids[i];
        sc[threadIdx.x]   = scales[i];
        rows[threadIdx.x] = g_inv[i] + g_base[e * NCHUNK + (i >> 8)];
    }
    __syncthreads();
    if (h >= H4) return;
    const float4* __restrict__ Gv = reinterpret_cast<const float4*>(G);
    float4* __restrict__ ov = reinterpret_cast<float4*>(out);
    float4 acc = make_float4(0.f, 0.f, 0.f, 0.f);
    for (int k = 0; k < K; k++) {
        const float  s = sc[k];
        const float4 v = __ldg(&Gv[(size_t)rows[k] * H4 + h]);
        acc.x = fmaf(s, v.x, acc.x);
        acc.y = fmaf(s, v.y, acc.y);
        acc.z = fmaf(s, v.z, acc.z);
        acc.w = fmaf(s, v.w, acc.w);
    }
    const size_t o = (size_t)b * H4 + h;
    ov[o] = acc;
    if (dup) ov[(size_t)B * H4 + o] = acc;
}

// ---------------------------------------------------------------------------
extern "C" void kernel_launch(void* const* d_in, const int* in_sizes, int n_in,
                              void* d_out, int out_size) {
    // metadata order: x[B,H] f32, expert_ids[B,K] i32, expert_scales[B,K] f32,
    //                 golden_expand_x[B*K,H] f32, moe_expert_num i32
    const int*   ids    = (const int*)  d_in[1];
    const float* scales = (const float*)d_in[2];
    const float* G      = (const float*)d_in[3];
    float*       out    = (float*)d_out;

    const int N  = in_sizes[1];                     // B*K = 32768
    const long long GH = (long long)in_sizes[3];    // N*H
    const int H  = (int)(GH / N);                   // 4096
    const int B  = in_sizes[0] / H;                 // 4096
    const int K  = N / B;                           // 8
    const int H4 = H >> 2;
    const int dup = (out_size >= 2 * B * H) ? 1 : 0;
    const int nchunk = (N + CHSZ - 1) / CHSZ;       // 128

    rank_wide_kernel<<<nchunk, CHSZ>>>(ids, N, nchunk);

    if (K == 8) {
        const int cpb = (H4 + 511) / 512;           // 512 float4 cols / block
        dim3 grid(cpb, B);                          // (2, 4096) for H=4096
        if ((H4 & 511) == 0)
            combine_kernel<8, false><<<grid, 256>>>(ids, G, scales, out,
                                                    B, H4, dup);
        else
            combine_kernel<8, true><<<grid, 256>>>(ids, G, scales, out,
                                                   B, H4, dup);
    } else {
        const int cpb = (H4 + 255) / 256;
        dim3 grid(cpb, B);
        combine_kernel_gen<<<grid, 256>>>(ids, G, scales, out, B, K, H4, dup);
    }
}

// round 16
// speedup vs baseline: 1.0325x; 1.0325x over previous
#include <cuda_runtime.h>

// ---------------------------------------------------------------------------
// MOE_DISTRIBUTE_CASCADE_GRAPH — locked best configuration (R13, 114.8us):
//   K1: wide rank — one block per 256-id chunk; chunk-local stable ranks via
//       one __match_any_sync step + per-chunk hist; ticket-elected LAST block
//       runs both scans (int4-vectorized) and re-arms the ticket.
//   K2: combine — 256 thr, TWO float4 cols/thread, 8192 blocks (best-measured
//       under reconstruction); inv rebuilt inline with PARALLEL dependent
//       loads: inv[i] = local_rank[i] + g_base[e][i>>8] + g_ebase[e].
// Verified dead ends: PDL (R9/R10), single-launch fusion (R8/R11), 1-col
// geometry (R14), base folding (R15), 1-SM rank (R2..R6,R12).
// ---------------------------------------------------------------------------

#define NBINS   256        // max experts supported (dataset uses 64)
#define NCHUNK  256        // max chunks (chunk = 256 ids -> N <= 65536)
#define CHSZ    256        // ids per chunk == threads per K1 block
#define MAXN    (NCHUNK * CHSZ)

__device__ int g_inv[MAXN];              // chunk-local ranks
__device__ int g_hist[NBINS * NCHUNK];   // [expert][chunk]  (expert-major)
__device__ int g_base[NBINS * NCHUNK];   // exclusive chunk prefix
__device__ int g_ebase[NBINS];           // exclusive expert prefix
__device__ unsigned g_ctr = 0;           // last-block ticket (self-resetting)

// --- K1: chunk-local stable ranks + hist; last block does both scans --------
__global__ void __launch_bounds__(CHSZ, 4)
rank_wide_kernel(const int* __restrict__ ids, int n, int nchunk) {
    __shared__ int cnt[8 * NBINS];
    __shared__ int totals[NBINS];
    __shared__ int is_last;
    const unsigned FULL = 0xffffffffu;
    const int blk  = blockIdx.x;
    const int tid  = threadIdx.x;
    const int w    = tid >> 5;
    const int lane = tid & 31;
    const int i    = blk * CHSZ + tid;

    for (int j = tid; j < 8 * NBINS; j += CHSZ) cnt[j] = 0;
    __syncthreads();

    // one match step per warp -> warp-local count/rank
    const bool valid = (i < n);
    const int  key   = valid ? ids[i] : (NBINS + lane);
    const unsigned mask = __match_any_sync(FULL, key);
    const int lower  = __popc(mask & ((1u << lane) - 1u));
    const int leader = __ffs(mask) - 1;
    if (valid && lane == leader)
        cnt[w * NBINS + key] = __popc(mask);
    __syncthreads();

    // per-expert exclusive scan over the 8 warp rows; totals -> g_hist
    {
        int run = 0;
        #pragma unroll
        for (int ww = 0; ww < 8; ww++) {
            const int h = cnt[ww * NBINS + tid];
            cnt[ww * NBINS + tid] = run;
            run += h;
        }
        g_hist[tid * NCHUNK + blk] = run;        // expert-major
    }
    __syncthreads();

    if (valid) g_inv[i] = lower + cnt[w * NBINS + key];

    // publish, then elect the last block
    __threadfence();
    __syncthreads();
    if (tid == 0)
        is_last = (atomicAdd(&g_ctr, 1u) == (unsigned)gridDim.x - 1u);
    __syncthreads();

    if (is_last) {
        __threadfence();                          // acquire all blocks' writes

        // scan A: per-expert exclusive prefix over chunks (int4-vectorized)
        int run = 0;
        if ((nchunk & 3) == 0) {
            const int4* hrow = reinterpret_cast<const int4*>(
                                   &g_hist[tid * NCHUNK]);
            int4* brow = reinterpret_cast<int4*>(&g_base[tid * NCHUNK]);
            #pragma unroll 8
            for (int c4 = 0; c4 < (nchunk >> 2); c4++) {
                const int4 h = hrow[c4];
                int4 bo;
                bo.x = run;
                bo.y = bo.x + h.x;
                bo.z = bo.y + h.y;
                bo.w = bo.z + h.z;
                run  = bo.w + h.w;
                brow[c4] = bo;
            }
        } else {
            #pragma unroll 8
            for (int c = 0; c < nchunk; c++) {
                const int h = g_hist[tid * NCHUNK + c];
                g_base[tid * NCHUNK + c] = run;
                run += h;
            }
        }
        totals[tid] = run;
        __syncthreads();

        // scan B: inclusive Hillis-Steele over expert totals (256 threads)
        #pragma unroll
        for (int d = 1; d < NBINS; d <<= 1) {
            const int v = (tid >= d) ? totals[tid - d] : 0;
            __syncthreads();
            totals[tid] += v;
            __syncthreads();
        }
        g_ebase[tid] = (tid == 0) ? 0 : totals[tid - 1];
        if (tid == 0) g_ctr = 0;                  // re-arm for next replay
    }
}

// --- K2: combine; reconstructs inv inline (parallel dependent loads) --------
template <int K, bool GUARD>
__global__ void __launch_bounds__(256, 4)
combine_kernel(const int* __restrict__ ids,
               const float* __restrict__ G,
               const float* __restrict__ scales,
               float* __restrict__ out,
               int B, int H4, int dup) {
    const int b  = blockIdx.y;
    const int h0 = blockIdx.x * 512 + threadIdx.x;
    const int h1 = h0 + 256;
    __shared__ int   rows[K];
    __shared__ float sc[K];
    if (threadIdx.x < K) {
        const int i = b * K + threadIdx.x;
        const int e = ids[i];
        sc[threadIdx.x]   = scales[i];
        // g_base and g_ebase depend only on e -> issued in parallel
        rows[threadIdx.x] = g_inv[i] + g_base[e * NCHUNK + (i >> 8)]
                                     + g_ebase[e];
    }
    __syncthreads();

    const float4* __restrict__ Gv = reinterpret_cast<const float4*>(G);
    float4* __restrict__ ov = reinterpret_cast<float4*>(out);

    const bool v0 = GUARD ? (h0 < H4) : true;
    const bool v1 = GUARD ? (h1 < H4) : true;
    float4 acc0 = make_float4(0.f, 0.f, 0.f, 0.f);
    float4 acc1 = make_float4(0.f, 0.f, 0.f, 0.f);
    #pragma unroll
    for (int k = 0; k < K; k++) {
        const float  s  = sc[k];
        const size_t rb = (size_t)rows[k] * H4;
        if (v0) {
            const float4 a = __ldg(&Gv[rb + h0]);
            acc0.x = fmaf(s, a.x, acc0.x);
            acc0.y = fmaf(s, a.y, acc0.y);
            acc0.z = fmaf(s, a.z, acc0.z);
            acc0.w = fmaf(s, a.w, acc0.w);
        }
        if (v1) {
            const float4 c = __ldg(&Gv[rb + h1]);
            acc1.x = fmaf(s, c.x, acc1.x);
            acc1.y = fmaf(s, c.y, acc1.y);
            acc1.z = fmaf(s, c.z, acc1.z);
            acc1.w = fmaf(s, c.w, acc1.w);
        }
    }
    const size_t ob = (size_t)b * H4;
    if (v0) ov[ob + h0] = acc0;
    if (v1) ov[ob + h1] = acc1;
    if (dup) {
        const size_t od = (size_t)B * H4 + ob;
        if (v0) ov[od + h0] = acc0;
        if (v1) ov[od + h1] = acc1;
    }
}

// generic-K fallback (same inline reconstruction)
__global__ void __launch_bounds__(256, 4)
combine_kernel_gen(const int* __restrict__ ids,
                   const float* __restrict__ G,
                   const float* __restrict__ scales,
                   float* __restrict__ out,
                   int B, int K, int H4, int dup) {
    const int b = blockIdx.y;
    const int h = blockIdx.x * 256 + threadIdx.x;
    __shared__ int   rows[32];
    __shared__ float sc[32];
    if (threadIdx.x < (unsigned)K) {
        const int i = b * K + threadIdx.x;
        const int e = ids[i];
        sc[threadIdx.x]   = scales[i];
        rows[threadIdx.x] = g_inv[i] + g_base[e * NCHUNK + (i >> 8)]
                                     + g_ebase[e];
    }
    __syncthreads();
    if (h >= H4) return;
    const float4* __restrict__ Gv = reinterpret_cast<const float4*>(G);
    float4* __restrict__ ov = reinterpret_cast<float4*>(out);
    float4 acc = make_float4(0.f, 0.f, 0.f, 0.f);
    for (int k = 0; k < K; k++) {
        const float  s = sc[k];
        const float4 v = __ldg(&Gv[(size_t)rows[k] * H4 + h]);
        acc.x = fmaf(s, v.x, acc.x);
        acc.y = fmaf(s, v.y, acc.y);
        acc.z = fmaf(s, v.z, acc.z);
        acc.w = fmaf(s, v.w, acc.w);
    }
    const size_t o = (size_t)b * H4 + h;
    ov[o] = acc;
    if (dup) ov[(size_t)B * H4 + o] = acc;
}

// ---------------------------------------------------------------------------
extern "C" void kernel_launch(void* const* d_in, const int* in_sizes, int n_in,
                              void* d_out, int out_size) {
    // metadata order: x[B,H] f32, expert_ids[B,K] i32, expert_scales[B,K] f32,
    //                 golden_expand_x[B*K,H] f32, moe_expert_num i32
    const int*   ids    = (const int*)  d_in[1];
    const float* scales = (const float*)d_in[2];
    const float* G      = (const float*)d_in[3];
    float*       out    = (float*)d_out;

    const int N  = in_sizes[1];                     // B*K = 32768
    const long long GH = (long long)in_sizes[3];    // N*H
    const int H  = (int)(GH / N);                   // 4096
    const int B  = in_sizes[0] / H;                 // 4096
    const int K  = N / B;                           // 8
    const int H4 = H >> 2;
    const int dup = (out_size >= 2 * B * H) ? 1 : 0;
    const int nchunk = (N + CHSZ - 1) / CHSZ;       // 128

    rank_wide_kernel<<<nchunk, CHSZ>>>(ids, N, nchunk);

    if (K == 8) {
        const int cpb = (H4 + 511) / 512;           // 512 float4 cols / block
        dim3 grid(cpb, B);
        if ((H4 & 511) == 0)
            combine_kernel<8, false><<<grid, 256>>>(ids, G, scales, out,
                                                    B, H4, dup);
        else
            combine_kernel<8, true><<<grid, 256>>>(ids, G, scales, out,
                                                   B, H4, dup);
    } else {
        const int cpb = (H4 + 255) / 256;
        dim3 grid(cpb, B);
        combine_kernel_gen<<<grid, 256>>>(ids, G, scales, out, B, K, H4, dup);
    }
}